// round 5
// baseline (speedup 1.0000x reference)
#include <cuda_runtime.h>

// BayesianMetaPosterior: scalar loss from two reductions.
//   S_sq  = sum(metamean^2)    over D elements
//   S_lg2 = sum(log2(fishers)) over M*D elements (scaled by ln2 at the end)
//   loss  = (M-1)*( S_sq/(2*sigma^2) + D*(log(sigma)+0.5*log(2pi)) )
//         + ( -0.5*M*D*log(2pi) + 0.5*ln2*S_lg2 )
// `means` (d_in[1]) is mathematically unused (Mahalanobis term == 0).
//
// Dynamic work-stealing over contiguous 32KB chunks (2048 float4): removes
// static-partition imbalance and per-SM speed spread. Unroll-8 front-batched
// streaming loads per chunk. Last-finished block finalizes.

#define NB   740            // 148 SMs * 5 CTAs (one wave @ 256 thr, ~48 regs)
#define NT   256
#define CHUNK_Q 2048        // float4 per chunk = 32 KB = one unroll-8 pass

__device__ double g_part_sq[NB];
__device__ double g_part_log[NB];
__device__ unsigned int g_chunk_ctr;    // zero-init; self-resets each run
__device__ unsigned int g_done_count;   // zero-init; self-resets each run

__device__ __forceinline__ double block_reduce(double v) {
    __shared__ double sm[NT / 32];
    #pragma unroll
    for (int off = 16; off > 0; off >>= 1)
        v += __shfl_down_sync(0xFFFFFFFFu, v, off);
    int lane = threadIdx.x & 31, warp = threadIdx.x >> 5;
    if (lane == 0) sm[warp] = v;
    __syncthreads();
    if (warp == 0) {
        v = (lane < NT / 32) ? sm[lane] : 0.0;
        #pragma unroll
        for (int off = 4; off > 0; off >>= 1)
            v += __shfl_down_sync(0xFFFFFFFFu, v, off);
    }
    return v;  // valid in thread 0
}

__global__ __launch_bounds__(NT, 5)
void bmp_kernel(const float* __restrict__ metamean,
                const float* __restrict__ fishers,
                long long D, long long MD, int M,
                float* __restrict__ out, int out_size)
{
    const float4* __restrict__ mm4 = reinterpret_cast<const float4*>(metamean);
    const float4* __restrict__ ff4 = reinterpret_cast<const float4*>(fishers);
    const long long n4m = D >> 2;    // D  % 4 == 0 for this problem
    const long long n4f = MD >> 2;   // MD % 4 == 0

    const unsigned int nCm = (unsigned int)((n4m + CHUNK_Q - 1) / CHUNK_Q);
    const unsigned int nCf = (unsigned int)((n4f + CHUNK_Q - 1) / CHUNK_Q);
    const unsigned int nC  = nCm + nCf;

    float sq0 = 0.f, sq1 = 0.f, sq2 = 0.f, sq3 = 0.f;
    float lg0 = 0.f, lg1 = 0.f, lg2_ = 0.f, lg3 = 0.f;

    __shared__ unsigned int s_chunk;

    for (;;) {
        if (threadIdx.x == 0)
            s_chunk = atomicAdd(&g_chunk_ctr, 1u);
        __syncthreads();
        const unsigned int c = s_chunk;
        __syncthreads();            // protect s_chunk before next overwrite
        if (c >= nC) break;

        const bool is_fish = (c >= nCm);
        const float4* __restrict__ base = is_fish ? ff4 : mm4;
        const long long cbase = (long long)(is_fish ? c - nCm : c) * CHUNK_Q;
        const long long hi    = (is_fish ? n4f : n4m);
        const long long q     = cbase + threadIdx.x;

        if (cbase + CHUNK_Q <= hi) {
            // ---- full chunk: 8 independent LDG.128 front-batched ----
            float4 v0 = __ldcs(base + q);
            float4 v1 = __ldcs(base + q + 1 * NT);
            float4 v2 = __ldcs(base + q + 2 * NT);
            float4 v3 = __ldcs(base + q + 3 * NT);
            float4 v4 = __ldcs(base + q + 4 * NT);
            float4 v5 = __ldcs(base + q + 5 * NT);
            float4 v6 = __ldcs(base + q + 6 * NT);
            float4 v7 = __ldcs(base + q + 7 * NT);
            if (is_fish) {
                lg0 += __log2f(v0.x) + __log2f(v0.y) + __log2f(v0.z) + __log2f(v0.w)
                     + __log2f(v4.x) + __log2f(v4.y) + __log2f(v4.z) + __log2f(v4.w);
                lg1 += __log2f(v1.x) + __log2f(v1.y) + __log2f(v1.z) + __log2f(v1.w)
                     + __log2f(v5.x) + __log2f(v5.y) + __log2f(v5.z) + __log2f(v5.w);
                lg2_ += __log2f(v2.x) + __log2f(v2.y) + __log2f(v2.z) + __log2f(v2.w)
                     + __log2f(v6.x) + __log2f(v6.y) + __log2f(v6.z) + __log2f(v6.w);
                lg3 += __log2f(v3.x) + __log2f(v3.y) + __log2f(v3.z) + __log2f(v3.w)
                     + __log2f(v7.x) + __log2f(v7.y) + __log2f(v7.z) + __log2f(v7.w);
            } else {
                sq0 += v0.x * v0.x + v0.y * v0.y + v0.z * v0.z + v0.w * v0.w
                     + v4.x * v4.x + v4.y * v4.y + v4.z * v4.z + v4.w * v4.w;
                sq1 += v1.x * v1.x + v1.y * v1.y + v1.z * v1.z + v1.w * v1.w
                     + v5.x * v5.x + v5.y * v5.y + v5.z * v5.z + v5.w * v5.w;
                sq2 += v2.x * v2.x + v2.y * v2.y + v2.z * v2.z + v2.w * v2.w
                     + v6.x * v6.x + v6.y * v6.y + v6.z * v6.z + v6.w * v6.w;
                sq3 += v3.x * v3.x + v3.y * v3.y + v3.z * v3.z + v3.w * v3.w
                     + v7.x * v7.x + v7.y * v7.y + v7.z * v7.z + v7.w * v7.w;
            }
        } else {
            // ---- partial (last) chunk: guarded ----
            #pragma unroll
            for (int u = 0; u < 8; u++) {
                long long qq = q + (long long)u * NT;
                if (qq < hi) {
                    float4 v = __ldcs(base + qq);
                    if (is_fish)
                        lg0 += __log2f(v.x) + __log2f(v.y)
                             + __log2f(v.z) + __log2f(v.w);
                    else
                        sq0 += v.x * v.x + v.y * v.y + v.z * v.z + v.w * v.w;
                }
            }
        }
    }

    double asq = ((double)sq0 + (double)sq1) + ((double)sq2 + (double)sq3);
    double alg = ((double)lg0 + (double)lg1) + ((double)lg2_ + (double)lg3);
    asq = block_reduce(asq);
    __syncthreads();
    alg = block_reduce(alg);

    __shared__ bool s_last;
    if (threadIdx.x == 0) {
        g_part_sq[blockIdx.x]  = asq;
        g_part_log[blockIdx.x] = alg;
        __threadfence();
        unsigned int prev = atomicAdd(&g_done_count, 1u);
        s_last = (prev == NB - 1);
    }
    __syncthreads();

    // ---- last block to finish performs the final reduction ----
    if (s_last) {
        double a = 0.0, b = 0.0;
        for (int k = threadIdx.x; k < NB; k += NT) {
            a += g_part_sq[k];
            b += g_part_log[k];
        }
        a = block_reduce(a);
        __syncthreads();
        b = block_reduce(b);
        if (threadIdx.x == 0) {
            const double log2pi = 1.8378770664093453;      // log(2*pi)
            const double logsig = -2.3025850929940456840;  // log(0.1)
            const double inv2s2 = 50.0;                    // 1/(2*0.1^2)
            const double ln2    = 0.6931471805599453;      // log2 -> ln
            double prior_term = (double)(M - 1) *
                (inv2s2 * a + (double)D * (logsig + 0.5 * log2pi));
            double post_term = -0.5 * (double)M * (double)D * log2pi
                               + 0.5 * ln2 * b;
            float loss = (float)(prior_term + post_term);
            for (int k = 0; k < out_size; k++) out[k] = loss;
            g_chunk_ctr  = 0;      // self-reset for next graph replay
            g_done_count = 0;
        }
    }
}

extern "C" void kernel_launch(void* const* d_in, const int* in_sizes, int n_in,
                              void* d_out, int out_size)
{
    const float* metamean = (const float*)d_in[0];
    // d_in[1] = means: unused (Mahalanobis term is identically zero)
    const float* fishers  = (const float*)d_in[2];

    const long long D  = (long long)in_sizes[0];
    const long long MD = (long long)in_sizes[2];
    const int M = (int)(MD / D);

    bmp_kernel<<<NB, NT>>>(metamean, fishers, D, MD, M,
                           (float*)d_out, out_size);
}